// round 15
// baseline (speedup 1.0000x reference)
#include <cuda_runtime.h>
#include <cuda_fp16.h>
#include <cstdint>

// GCN on GB300 (base sm_103 PTX only: mma.sync + ldmatrix + cp.async).
// out = relu( D^-1/2 A D^-1/2 (G @ W) + bias ), plus verbatim adj copy.
// B=16, N=4096, F=64.
// R15: GEMM launched as 296 CTAs = exactly the co-residency slot count
// (148 SMs x occ 2). bids 0..255 = GEMM tiles (R12 mainloop, unchanged);
// bids 256..295 = dedicated adj->tail copy CTAs that fill the 40 slots the
// 256-tile GEMM leaves idle -> the 64MB copy runs concurrently for free.

#define NN 4096
#define FF 64
#define BB 16

// ---- scratch (static device arrays: allowed) ----
__device__ float g_dinv[NN];
__device__ __half g_adj_h[(size_t)NN * NN];          // fp16 adj (L2-resident for GEMM)
__device__ __half g_bT_h[(size_t)BB * FF * NN];      // fp16 S2' [c=b*64+o][m], dinv folded

// ---------------------------------------------------------------------------
// helpers (base-PTX only)
// ---------------------------------------------------------------------------
__device__ __forceinline__ uint32_t smem_u32(const void* p) {
    uint32_t a;
    asm("{ .reg .u64 t; cvta.to.shared.u64 t, %1; cvt.u32.u64 %0, t; }" : "=r"(a) : "l"(p));
    return a;
}
#define CP_ASYNC16(dst, src) \
    asm volatile("cp.async.cg.shared.global [%0], [%1], 16;" :: "r"(dst), "l"(src) : "memory")
#define CP_COMMIT()  asm volatile("cp.async.commit_group;" ::: "memory")
#define CP_WAIT1()   asm volatile("cp.async.wait_group 1;" ::: "memory")
#define CP_WAIT0()   asm volatile("cp.async.wait_group 0;" ::: "memory")

#define LDMATRIX_X4(r0, r1, r2, r3, addr) \
    asm volatile("ldmatrix.sync.aligned.m8n8.x4.shared.b16 {%0,%1,%2,%3}, [%4];" \
        : "=r"(r0), "=r"(r1), "=r"(r2), "=r"(r3) : "r"(addr))

// D = A*B + D, m16n8k16, fp16 in / fp32 acc (base PTX, sm_80+)
#define MMA16816(c, a, b) \
    asm volatile("mma.sync.aligned.m16n8k16.row.col.f32.f16.f16.f32 " \
        "{%0,%1,%2,%3}, {%4,%5,%6,%7}, {%8,%9}, {%0,%1,%2,%3};" \
        : "+f"((c)[0]), "+f"((c)[1]), "+f"((c)[2]), "+f"((c)[3]) \
        : "r"((a)[0]), "r"((a)[1]), "r"((a)[2]), "r"((a)[3]), \
          "r"((b)[0]), "r"((b)[1]))

__device__ __forceinline__ uint32_t pack_h2(__half a, __half b) {
    uint32_t lo = reinterpret_cast<unsigned short&>(a);
    uint32_t hi = reinterpret_cast<unsigned short&>(b);
    return lo | (hi << 16);
}

// ---------------------------------------------------------------------------
// 1) fused: row sums -> d^{-1/2}  +  adj -> fp16  (copy lives in the GEMM)
//    R10-measured at 17.2us.
// ---------------------------------------------------------------------------
__global__ __launch_bounds__(256)
void rowsum_split_kernel(const float* __restrict__ adj) {
    __shared__ float red[8];
    int row = blockIdx.x;
    const float4* r = (const float4*)(adj + ((size_t)row << 12));
    uint2* oh = (uint2*)g_adj_h + ((size_t)row << 10);
    float s = 0.f;
    for (int i = threadIdx.x; i < NN / 4; i += 256) {
        float4 v = __ldcs(r + i);
        s += (v.x + v.y) + (v.z + v.w);
        oh[i] = make_uint2(pack_h2(__float2half_rn(v.x), __float2half_rn(v.y)),
                           pack_h2(__float2half_rn(v.z), __float2half_rn(v.w)));
    }
    #pragma unroll
    for (int off = 16; off; off >>= 1) s += __shfl_xor_sync(0xffffffffu, s, off);
    if ((threadIdx.x & 31) == 0) red[threadIdx.x >> 5] = s;
    __syncthreads();
    if (threadIdx.x < 8) {
        s = red[threadIdx.x];
        #pragma unroll
        for (int off = 4; off; off >>= 1) s += __shfl_xor_sync(0xffu, s, off);
        if (threadIdx.x == 0) {
            if (s == 0.f) s = 1.f;
            g_dinv[row] = rsqrtf(s);
        }
    }
}

// ---------------------------------------------------------------------------
// 2) support: S2'[c][m] = dinv[m] * (graph @ W)[b][m][o], TRANSPOSED fp16.
//    2-barrier restaged version (R12-proven).
// ---------------------------------------------------------------------------
__global__ __launch_bounds__(256)
void support_kernel(const float* __restrict__ graph, const float* __restrict__ weight) {
    __shared__ float gsm[64][65];
    __shared__ float Ssm[64][65];
    int tid = threadIdx.x;
    int o = tid & 63;
    int grp = tid >> 6;
    int b = blockIdx.y;
    int mb = blockIdx.x * 64;

    float w[FF];
    #pragma unroll
    for (int i = 0; i < FF; i++) w[i] = weight[i * FF + o];

    #pragma unroll
    for (int it = 0; it < 16; it++) {
        int r = it * 4 + grp;
        gsm[r][o] = graph[(((size_t)b << 12) + mb + r) * FF + o];
    }
    __syncthreads();

    #pragma unroll
    for (int it = 0; it < 16; it++) {
        int r = it * 4 + grp;
        float acc = 0.f;
        #pragma unroll
        for (int i = 0; i < FF; i++) acc = fmaf(gsm[r][i], w[i], acc);
        Ssm[r][o] = acc * g_dinv[mb + r];
    }
    __syncthreads();

    int o2 = tid >> 2;
    int rq = tid & 3;
    uint32_t ph[8];
    #pragma unroll
    for (int p = 0; p < 8; p++) {
        float v0 = Ssm[rq * 16 + 2 * p][o2];
        float v1 = Ssm[rq * 16 + 2 * p + 1][o2];
        ph[p] = pack_h2(__float2half_rn(v0), __float2half_rn(v1));
    }
    size_t base = (((size_t)(b * 64 + o2)) << 12) + mb + rq * 16;
    uint4* dh = (uint4*)(g_bT_h + base);
    dh[0] = make_uint4(ph[0], ph[1], ph[2], ph[3]);
    dh[1] = make_uint4(ph[4], ph[5], ph[6], ph[7]);
}

// ---------------------------------------------------------------------------
// 3) main GEMM + co-resident copy. Grid = 296 CTAs = 148 SMs x occ 2.
//    bids 0..255: GEMM tile (exact R12 mainloop: CTA 128x128, 8 warps,
//    warp 32x64, BK=64, 2-stage cp.async, 144B-padded rows).
//    bids 256..295: adj->tail copy only (fills the 40 idle slots).
// ---------------------------------------------------------------------------
#define BKK 64
#define KT_ITERS (NN / BKK)          // 64
#define ROW_B 144
#define VER_B (128 * ROW_B)          // 18432
#define STAGE_B (2 * VER_B)          // 36864
#define SMEM_DYN (2 * STAGE_B)       // 73728
#define N_GEMM_CTAS 256
#define N_COPY_CTAS 40
#define GRID_TOTAL (N_GEMM_CTAS + N_COPY_CTAS)   // 296
#define NCHUNK 256                   // 16.7M floats in 256KB chunks
#define CHUNK_F4 16384               // float4 per chunk

__global__ __launch_bounds__(256, 2)
void gemm_mma_kernel(const float* __restrict__ bias, float* __restrict__ out,
                     const float4* __restrict__ adj4, float4* __restrict__ tail4) {
    extern __shared__ char smem[];
    __shared__ float s_bias[64];
    int tid = threadIdx.x;
    int bid = blockIdx.x;

    if (bid >= N_GEMM_CTAS) {
        // ---- dedicated copy CTA: ~6.4 chunks (1.6MB) each, touch-once ----
        for (int c = bid - N_GEMM_CTAS; c < NCHUNK; c += N_COPY_CTAS) {
            const float4* src = adj4 + (size_t)c * CHUNK_F4;
            float4* dst = tail4 + (size_t)c * CHUNK_F4;
            #pragma unroll 4
            for (int i = tid; i < CHUNK_F4; i += 256)
                __stcs(dst + i, __ldcs(src + i));
        }
        return;
    }

    uint32_t sb = smem_u32(smem);
    int bx = bid & 7;         // 0..7  (128-col blocks)
    int by = bid >> 3;        // 0..31 (128-row blocks)
    int wid = tid >> 5, lane = tid & 31;
    int wm = wid >> 1, wn = wid & 1;         // warp grid 4(m) x 2(n)
    int g = lane >> 2, tg = lane & 3;        // epilogue frag ids

    if (tid < 64) s_bias[tid] = bias[tid];

    // ---- cp.async stage loader: 2048 x 16B chunks, 8 per thread ----
    auto load_stage = [&](int s, int kt) {
        uint32_t st = sb + (uint32_t)s * STAGE_B;
        int col0 = kt * BKK;                 // half-elem offset along K
        #pragma unroll
        for (int q = tid; q < 2048; q += 256) {
            int region = q >> 10;            // 0=A 1=B
            int l = q & 1023;
            int row = l >> 3;
            int c = l & 7;                   // 16B chunk within 128B of data
            const __half* base = region ? g_bT_h : g_adj_h;
            int grow = (region ? bx : by) * 128 + row;
            const __half* src = base + ((size_t)grow << 12) + col0 + c * 8;
            uint32_t dst = st + (uint32_t)region * VER_B + row * ROW_B + c * 16;
            CP_ASYNC16(dst, src);
        }
        CP_COMMIT();
    };

    // ldmatrix lane-address components (proven in R8)
    int a_row_l = (lane & 7) + ((lane >> 3) & 1) * 8;
    int a_colh_l = (lane >> 4) * 8;
    int b_row_l = ((lane >> 4) & 1) * 8 + (lane & 7);
    int b_colh_l = ((lane >> 3) & 1) * 8;

    float acc[2][8][4];
    #pragma unroll
    for (int mi = 0; mi < 2; mi++)
        #pragma unroll
        for (int nj = 0; nj < 8; nj++)
            #pragma unroll
            for (int c = 0; c < 4; c++) acc[mi][nj][c] = 0.f;

    load_stage(0, 0);

    #pragma unroll 1
    for (int kt = 0; kt < KT_ITERS; kt++) {
        if (kt + 1 < KT_ITERS) {
            load_stage((kt + 1) & 1, kt + 1);
            CP_WAIT1();
        } else {
            CP_WAIT0();
        }
        __syncthreads();

        uint32_t st = sb + (uint32_t)(kt & 1) * STAGE_B;
        uint32_t aBase = st + (uint32_t)((wm * 32 + a_row_l) * ROW_B + a_colh_l * 2);
        uint32_t bBase = st + VER_B + (uint32_t)((wn * 64 + b_row_l) * ROW_B + b_colh_l * 2);

        #pragma unroll
        for (int s = 0; s < 4; s++) {        // four k16 steps per BK=64
            uint32_t ah[2][4], bh[8][2];
            #pragma unroll
            for (int mi = 0; mi < 2; mi++) {
                uint32_t addr = aBase + (uint32_t)(mi * 16 * ROW_B + s * 32);
                LDMATRIX_X4(ah[mi][0], ah[mi][1], ah[mi][2], ah[mi][3], addr);
            }
            #pragma unroll
            for (int p = 0; p < 4; p++) {    // each x4 covers nj=2p, 2p+1
                uint32_t addr = bBase + (uint32_t)(p * 16 * ROW_B + s * 32);
                LDMATRIX_X4(bh[2 * p][0], bh[2 * p][1], bh[2 * p + 1][0], bh[2 * p + 1][1], addr);
            }
            #pragma unroll
            for (int mi = 0; mi < 2; mi++)
                #pragma unroll
                for (int nj = 0; nj < 8; nj++) MMA16816(acc[mi][nj], ah[mi], bh[nj]);
        }
        __syncthreads();
    }

    // ---- epilogue: relu(dinv[n]*acc + bias[o]) -> out[b][n][o] ----
    int b_out = bx * 2 + wn;                      // batch slice (cols/64)
    float* obase = out + ((size_t)b_out << 18);
    #pragma unroll
    for (int mi = 0; mi < 2; mi++) {
        int r0 = by * 128 + wm * 32 + mi * 16 + g;
        int r1 = r0 + 8;
        float d0 = g_dinv[r0];
        float d1 = g_dinv[r1];
        #pragma unroll
        for (int nj = 0; nj < 8; nj++) {
            int o = nj * 8 + tg * 2;
            float bz0 = s_bias[o], bz1 = s_bias[o + 1];
            float2 v0, v1;
            v0.x = fmaxf(fmaf(acc[mi][nj][0], d0, bz0), 0.f);
            v0.y = fmaxf(fmaf(acc[mi][nj][1], d0, bz1), 0.f);
            v1.x = fmaxf(fmaf(acc[mi][nj][2], d1, bz0), 0.f);
            v1.y = fmaxf(fmaf(acc[mi][nj][3], d1, bz1), 0.f);
            *(float2*)(obase + ((size_t)r0 << 6) + o) = v0;
            *(float2*)(obase + ((size_t)r1 << 6) + o) = v1;
        }
    }
}

// ---------------------------------------------------------------------------
extern "C" void kernel_launch(void* const* d_in, const int* in_sizes, int n_in,
                              void* d_out, int out_size) {
    const float* graph  = (const float*)d_in[0];   // [16,4096,64]
    const float* adj    = (const float*)d_in[1];   // [4096,4096]
    const float* weight = (const float*)d_in[2];   // [64,64]
    const float* bias   = (const float*)d_in[3];   // [64]
    float* out = (float*)d_out;

    cudaFuncSetAttribute(gemm_mma_kernel,
                         cudaFuncAttributeMaxDynamicSharedMemorySize, SMEM_DYN);

    const int out_elems = BB * NN * FF;            // 4,194,304
    float* tail = out + out_elems;                 // adj copy destination

    rowsum_split_kernel<<<NN, 256>>>(adj);
    support_kernel<<<dim3(NN / 64, BB), 256>>>(graph, weight);
    gemm_mma_kernel<<<GRID_TOTAL, 256, SMEM_DYN>>>(bias, out,
                                                   (const float4*)adj,
                                                   (float4*)tail);
}

// round 16
// speedup vs baseline: 1.6348x; 1.6348x over previous
#include <cuda_runtime.h>
#include <cuda_fp16.h>
#include <cstdint>

// GCN on GB300 (base sm_103 PTX only: mma.sync + ldmatrix + cp.async).
// out = relu( D^-1/2 A D^-1/2 (G @ W) + bias ), plus verbatim adj copy.
// B=16, N=4096, F=64.
// FINAL architecture (R14 = measured best 175.1us):
//   1) fused rowsum + fp32->fp16 split + verbatim copy (adj read once),
//      R12 loop structure + touch-once cache hints.
//   2) support GEMM (G@W, dinv folded), transposed fp16 write, 2 barriers.
//   3) fp16 single-pass HMMA GEMM, 128x128 tiles, BK=64, 2-stage cp.async,
//      ldmatrix.x4 fragments, fused dinv/bias/relu epilogue.
//      (~95% of the sm_103 legacy-HMMA issue floor; R9/R11/R13/R15
//       restructuring experiments all regressed or were neutral.)

#define NN 4096
#define FF 64
#define BB 16

// ---- scratch (static device arrays: allowed) ----
__device__ float g_dinv[NN];
__device__ __half g_adj_h[(size_t)NN * NN];          // fp16 adj (L2-resident for GEMM)
__device__ __half g_bT_h[(size_t)BB * FF * NN];      // fp16 S2' [c=b*64+o][m], dinv folded

// ---------------------------------------------------------------------------
// helpers (base-PTX only)
// ---------------------------------------------------------------------------
__device__ __forceinline__ uint32_t smem_u32(const void* p) {
    uint32_t a;
    asm("{ .reg .u64 t; cvta.to.shared.u64 t, %1; cvt.u32.u64 %0, t; }" : "=r"(a) : "l"(p));
    return a;
}
#define CP_ASYNC16(dst, src) \
    asm volatile("cp.async.cg.shared.global [%0], [%1], 16;" :: "r"(dst), "l"(src) : "memory")
#define CP_COMMIT()  asm volatile("cp.async.commit_group;" ::: "memory")
#define CP_WAIT1()   asm volatile("cp.async.wait_group 1;" ::: "memory")
#define CP_WAIT0()   asm volatile("cp.async.wait_group 0;" ::: "memory")

#define LDMATRIX_X4(r0, r1, r2, r3, addr) \
    asm volatile("ldmatrix.sync.aligned.m8n8.x4.shared.b16 {%0,%1,%2,%3}, [%4];" \
        : "=r"(r0), "=r"(r1), "=r"(r2), "=r"(r3) : "r"(addr))

// D = A*B + D, m16n8k16, fp16 in / fp32 acc (base PTX, sm_80+)
#define MMA16816(c, a, b) \
    asm volatile("mma.sync.aligned.m16n8k16.row.col.f32.f16.f16.f32 " \
        "{%0,%1,%2,%3}, {%4,%5,%6,%7}, {%8,%9}, {%0,%1,%2,%3};" \
        : "+f"((c)[0]), "+f"((c)[1]), "+f"((c)[2]), "+f"((c)[3]) \
        : "r"((a)[0]), "r"((a)[1]), "r"((a)[2]), "r"((a)[3]), \
          "r"((b)[0]), "r"((b)[1]))

__device__ __forceinline__ uint32_t pack_h2(__half a, __half b) {
    uint32_t lo = reinterpret_cast<unsigned short&>(a);
    uint32_t hi = reinterpret_cast<unsigned short&>(b);
    return lo | (hi << 16);
}

// ---------------------------------------------------------------------------
// 1) fused: row sums -> d^{-1/2}  +  adj -> fp16  +  adj -> output tail copy.
//    adj read and tail write are touch-once -> __ldcs/__stcs (evict-first);
//    fp16-plane store stays default policy so it parks in L2 for the GEMM.
// ---------------------------------------------------------------------------
__global__ __launch_bounds__(256)
void rowsum_split_copy_kernel(const float* __restrict__ adj, float* __restrict__ out_tail) {
    __shared__ float red[8];
    int row = blockIdx.x;
    const float4* r = (const float4*)(adj + ((size_t)row << 12));
    float4* cp = (float4*)(out_tail + ((size_t)row << 12));
    uint2* oh = (uint2*)g_adj_h + ((size_t)row << 10);
    float s = 0.f;
    for (int i = threadIdx.x; i < NN / 4; i += 256) {
        float4 v = __ldcs(r + i);
        s += (v.x + v.y) + (v.z + v.w);
        oh[i] = make_uint2(pack_h2(__float2half_rn(v.x), __float2half_rn(v.y)),
                           pack_h2(__float2half_rn(v.z), __float2half_rn(v.w)));
        __stcs(cp + i, v);
    }
    #pragma unroll
    for (int off = 16; off; off >>= 1) s += __shfl_xor_sync(0xffffffffu, s, off);
    if ((threadIdx.x & 31) == 0) red[threadIdx.x >> 5] = s;
    __syncthreads();
    if (threadIdx.x < 8) {
        s = red[threadIdx.x];
        #pragma unroll
        for (int off = 4; off; off >>= 1) s += __shfl_xor_sync(0xffu, s, off);
        if (threadIdx.x == 0) {
            if (s == 0.f) s = 1.f;
            g_dinv[row] = rsqrtf(s);
        }
    }
}

// ---------------------------------------------------------------------------
// 2) support: S2'[c][m] = dinv[m] * (graph @ W)[b][m][o], TRANSPOSED fp16.
//    2-barrier restaged version (R12-proven).
// ---------------------------------------------------------------------------
__global__ __launch_bounds__(256)
void support_kernel(const float* __restrict__ graph, const float* __restrict__ weight) {
    __shared__ float gsm[64][65];
    __shared__ float Ssm[64][65];
    int tid = threadIdx.x;
    int o = tid & 63;
    int grp = tid >> 6;
    int b = blockIdx.y;
    int mb = blockIdx.x * 64;

    float w[FF];
    #pragma unroll
    for (int i = 0; i < FF; i++) w[i] = weight[i * FF + o];

    #pragma unroll
    for (int it = 0; it < 16; it++) {
        int r = it * 4 + grp;
        gsm[r][o] = graph[(((size_t)b << 12) + mb + r) * FF + o];
    }
    __syncthreads();

    #pragma unroll
    for (int it = 0; it < 16; it++) {
        int r = it * 4 + grp;
        float acc = 0.f;
        #pragma unroll
        for (int i = 0; i < FF; i++) acc = fmaf(gsm[r][i], w[i], acc);
        Ssm[r][o] = acc * g_dinv[mb + r];
    }
    __syncthreads();

    int o2 = tid >> 2;
    int rq = tid & 3;
    uint32_t ph[8];
    #pragma unroll
    for (int p = 0; p < 8; p++) {
        float v0 = Ssm[rq * 16 + 2 * p][o2];
        float v1 = Ssm[rq * 16 + 2 * p + 1][o2];
        ph[p] = pack_h2(__float2half_rn(v0), __float2half_rn(v1));
    }
    size_t base = (((size_t)(b * 64 + o2)) << 12) + mb + rq * 16;
    uint4* dh = (uint4*)(g_bT_h + base);
    dh[0] = make_uint4(ph[0], ph[1], ph[2], ph[3]);
    dh[1] = make_uint4(ph[4], ph[5], ph[6], ph[7]);
}

// ---------------------------------------------------------------------------
// 3) main GEMM (exact R12/R14): CTA 128x128, 8 warps (4m x 2n), warp 32x64,
//    BK=64, 2-stage cp.async. smem rows padded to 144B: ldmatrix phases
//    conflict-free.
// ---------------------------------------------------------------------------
#define BKK 64
#define KT_ITERS (NN / BKK)          // 64
#define ROW_B 144
#define VER_B (128 * ROW_B)          // 18432
#define STAGE_B (2 * VER_B)          // 36864
#define SMEM_DYN (2 * STAGE_B)       // 73728

__global__ __launch_bounds__(256, 2)
void gemm_mma_kernel(const float* __restrict__ bias, float* __restrict__ out) {
    extern __shared__ char smem[];
    __shared__ float s_bias[64];
    uint32_t sb = smem_u32(smem);
    int tid = threadIdx.x;
    int bx = blockIdx.x;      // 0..7  (128-col blocks)
    int by = blockIdx.y;      // 0..31 (128-row blocks)
    int wid = tid >> 5, lane = tid & 31;
    int wm = wid >> 1, wn = wid & 1;         // warp grid 4(m) x 2(n)
    int g = lane >> 2, tg = lane & 3;        // epilogue frag ids

    if (tid < 64) s_bias[tid] = bias[tid];

    // ---- cp.async stage loader: 2048 x 16B chunks, 8 per thread ----
    auto load_stage = [&](int s, int kt) {
        uint32_t st = sb + (uint32_t)s * STAGE_B;
        int col0 = kt * BKK;                 // half-elem offset along K
        #pragma unroll
        for (int q = tid; q < 2048; q += 256) {
            int region = q >> 10;            // 0=A 1=B
            int l = q & 1023;
            int row = l >> 3;
            int c = l & 7;                   // 16B chunk within 128B of data
            const __half* base = region ? g_bT_h : g_adj_h;
            int grow = (region ? bx : by) * 128 + row;
            const __half* src = base + ((size_t)grow << 12) + col0 + c * 8;
            uint32_t dst = st + (uint32_t)region * VER_B + row * ROW_B + c * 16;
            CP_ASYNC16(dst, src);
        }
        CP_COMMIT();
    };

    // ldmatrix lane-address components (proven in R8)
    int a_row_l = (lane & 7) + ((lane >> 3) & 1) * 8;
    int a_colh_l = (lane >> 4) * 8;
    int b_row_l = ((lane >> 4) & 1) * 8 + (lane & 7);
    int b_colh_l = ((lane >> 3) & 1) * 8;

    float acc[2][8][4];
    #pragma unroll
    for (int mi = 0; mi < 2; mi++)
        #pragma unroll
        for (int nj = 0; nj < 8; nj++)
            #pragma unroll
            for (int c = 0; c < 4; c++) acc[mi][nj][c] = 0.f;

    load_stage(0, 0);

    #pragma unroll 1
    for (int kt = 0; kt < KT_ITERS; kt++) {
        if (kt + 1 < KT_ITERS) {
            load_stage((kt + 1) & 1, kt + 1);
            CP_WAIT1();
        } else {
            CP_WAIT0();
        }
        __syncthreads();

        uint32_t st = sb + (uint32_t)(kt & 1) * STAGE_B;
        uint32_t aBase = st + (uint32_t)((wm * 32 + a_row_l) * ROW_B + a_colh_l * 2);
        uint32_t bBase = st + VER_B + (uint32_t)((wn * 64 + b_row_l) * ROW_B + b_colh_l * 2);

        #pragma unroll
        for (int s = 0; s < 4; s++) {        // four k16 steps per BK=64
            uint32_t ah[2][4], bh[8][2];
            #pragma unroll
            for (int mi = 0; mi < 2; mi++) {
                uint32_t addr = aBase + (uint32_t)(mi * 16 * ROW_B + s * 32);
                LDMATRIX_X4(ah[mi][0], ah[mi][1], ah[mi][2], ah[mi][3], addr);
            }
            #pragma unroll
            for (int p = 0; p < 4; p++) {    // each x4 covers nj=2p, 2p+1
                uint32_t addr = bBase + (uint32_t)(p * 16 * ROW_B + s * 32);
                LDMATRIX_X4(bh[2 * p][0], bh[2 * p][1], bh[2 * p + 1][0], bh[2 * p + 1][1], addr);
            }
            #pragma unroll
            for (int mi = 0; mi < 2; mi++)
                #pragma unroll
                for (int nj = 0; nj < 8; nj++) MMA16816(acc[mi][nj], ah[mi], bh[nj]);
        }
        __syncthreads();
    }

    // ---- epilogue: relu(dinv[n]*acc + bias[o]) -> out[b][n][o] ----
    int b_out = bx * 2 + wn;                      // batch slice (cols/64)
    float* obase = out + ((size_t)b_out << 18);
    #pragma unroll
    for (int mi = 0; mi < 2; mi++) {
        int r0 = by * 128 + wm * 32 + mi * 16 + g;
        int r1 = r0 + 8;
        float d0 = g_dinv[r0];
        float d1 = g_dinv[r1];
        #pragma unroll
        for (int nj = 0; nj < 8; nj++) {
            int o = nj * 8 + tg * 2;
            float bz0 = s_bias[o], bz1 = s_bias[o + 1];
            float2 v0, v1;
            v0.x = fmaxf(fmaf(acc[mi][nj][0], d0, bz0), 0.f);
            v0.y = fmaxf(fmaf(acc[mi][nj][1], d0, bz1), 0.f);
            v1.x = fmaxf(fmaf(acc[mi][nj][2], d1, bz0), 0.f);
            v1.y = fmaxf(fmaf(acc[mi][nj][3], d1, bz1), 0.f);
            *(float2*)(obase + ((size_t)r0 << 6) + o) = v0;
            *(float2*)(obase + ((size_t)r1 << 6) + o) = v1;
        }
    }
}

// ---------------------------------------------------------------------------
extern "C" void kernel_launch(void* const* d_in, const int* in_sizes, int n_in,
                              void* d_out, int out_size) {
    const float* graph  = (const float*)d_in[0];   // [16,4096,64]
    const float* adj    = (const float*)d_in[1];   // [4096,4096]
    const float* weight = (const float*)d_in[2];   // [64,64]
    const float* bias   = (const float*)d_in[3];   // [64]
    float* out = (float*)d_out;

    cudaFuncSetAttribute(gemm_mma_kernel,
                         cudaFuncAttributeMaxDynamicSharedMemorySize, SMEM_DYN);

    const int out_elems = BB * NN * FF;            // 4,194,304
    float* tail = out + out_elems;                 // adj copy destination

    rowsum_split_copy_kernel<<<NN, 256>>>(adj, tail);
    support_kernel<<<dim3(NN / 64, BB), 256>>>(graph, weight);
    gemm_mma_kernel<<<dim3(8, 32), 256, SMEM_DYN>>>(bias, out);
}